// round 15
// baseline (speedup 1.0000x reference)
#include <cuda_runtime.h>
#include <cstdint>

#define NTT 144
#define NLMAX 14
#define RPB 32                    // rows per block
#define TPR 4                     // threads per row
#define NGRP 9                    // element offset = g*16 + l*4
#define GSTRIDE 16
#define BLK (RPB * TPR)           // 128 = 4 full warps
#define RCS 17                    // rcu row stride in ull (136B -> bank-conflict-free)

#define F_TAU 1.8f
#define F_INV_T1B (1.0f/1.65f)
#define F_LOG2E 1.4426950408889634f
#define F_DEG2RAD 0.017453292519943295f

typedef unsigned long long ull;

// per-stripe series depths, calibrated to the same tail level as 14 terms @ x=6.27
__device__ constexpr int NLG[NGRP] = {9, 9, 10, 11, 11, 12, 13, 13, 14};
__device__ constexpr int NSG[NGRP] = {4, 5,  6,  6,  7,  8,  8,  9, 10};

__device__ __forceinline__ ull pack2(float lo, float hi) {
    ull r;
    asm("mov.b64 %0, {%1, %2};" : "=l"(r) : "f"(lo), "f"(hi));
    return r;
}
__device__ __forceinline__ void unpack2(ull v, float& lo, float& hi) {
    asm("mov.b64 {%0, %1}, %2;" : "=f"(lo), "=f"(hi) : "l"(v));
}
__device__ __forceinline__ ull ffma2(ull a, ull b, ull c) {
    ull d;
    asm("fma.rn.f32x2 %0, %1, %2, %3;" : "=l"(d) : "l"(a), "l"(b), "l"(c));
    return d;
}
__device__ __forceinline__ ull fmul2(ull a, ull b) {
    ull d;
    asm("mul.rn.f32x2 %0, %1, %2;" : "=l"(d) : "l"(a), "l"(b));
    return d;
}
__device__ __forceinline__ ull fadd2(ull a, ull b) {
    ull d;
    asm("add.rn.f32x2 %0, %1, %2;" : "=l"(d) : "l"(a), "l"(b));
    return d;
}
// sign-flip both packed lanes — no persistent constant register needed
__device__ __forceinline__ ull neg2(ull v) {
    ull r;
    asm("xor.b64 %0, %1, 0x8000000080000000;" : "=l"(r) : "l"(v));
    return r;
}
// {-log2e, -log2e} materialized per use; volatile blocks hoisting into a reg
__device__ __forceinline__ ull nl2e_imm() {
    ull r;
    asm volatile("mov.b64 %0, 0xBFB8AA3BBFB8AA3B;" : "=l"(r));
    return r;
}
__device__ __forceinline__ float fast_lg2(float x) {
    float r;
    asm("lg2.approx.f32 %0, %1;" : "=f"(r) : "f"(x));
    return r;
}
__device__ __forceinline__ float fast_ex2(float x) {
    float r;
    asm("ex2.approx.f32 %0, %1;" : "=f"(r) : "f"(x));
    return r;
}
// forced single load into a register pair — ptxas cannot rematerialize this
__device__ __forceinline__ ull lds64(uint32_t saddr) {
    ull v;
    asm volatile("ld.shared.b64 %0, [%1];" : "=l"(v) : "r"(saddr));
    return v;
}

__global__ __launch_bounds__(BLK, 11)
void dynangio_kernel(const float4* __restrict__ x,
                     const float*  __restrict__ t,
                     const float*  __restrict__ alpha,
                     const float*  __restrict__ R,
                     float*        __restrict__ out,
                     int rows)
{
    __shared__ __align__(16) float tsh[NTT];
    __shared__ __align__(16) float cpos[NTT];   //  R*sin(alpha)
    // per-row packed coefficients {d,d} (C folded in), + packed scalars:
    // [NLMAX] = {a, sp}, [NLMAX+1] = {q, shift}; padded stride RCS for banks
    __shared__ __align__(16) ull rcu[RPB][RCS];

    const int tid = threadIdx.x;

    for (int j = tid; j < NTT; j += BLK) {
        tsh[j] = t[j];
        cpos[j] = R[j] * __sinf(alpha[j] * F_DEG2RAD);
    }

    if (tid < RPB) {
        int row = blockIdx.x * RPB + tid;
        if (row < rows) {
            float4 xv = x[row];
            float dt  = xv.x;
            float s   = xv.y;
            float p   = xv.z;
            float amp = xv.w;

            float u  = p * s;          // a - 1 in [0,1)
            float a  = 1.0f + u;
            float sp = s + F_INV_T1B;  // sprime

            // C = amp * 2 * exp(-dt/T1B) * (s/sp)^a   (base-2)
            float ratio = __fdividef(s, sp);
            float ex = fmaf(a, fast_lg2(ratio), -dt * (F_LOG2E * F_INV_T1B));
            float C  = amp * 2.0f * fast_ex2(ex);

            // Gamma(1+u), A&S 6.1.36
            float g;
            g = fmaf(u,  0.035868343f, -0.193527818f);
            g = fmaf(u, g,  0.482199394f);
            g = fmaf(u, g, -0.756704078f);
            g = fmaf(u, g,  0.918206857f);
            g = fmaf(u, g, -0.897056937f);
            g = fmaf(u, g,  0.988205891f);
            g = fmaf(u, g, -0.577191652f);
            g = fmaf(u, g,  1.0f);

            // Gamma(a+NLMAX) by product, one reciprocal, build d_n downward
            float prod = a * g;
            #pragma unroll
            for (int k = 1; k < NLMAX; k++) prod *= (a + (float)k);
            float d = __frcp_rn(prod);
            float cd = C * d;
            rcu[tid][NLMAX - 1] = pack2(cd, cd);
            #pragma unroll
            for (int n = NLMAX - 1; n >= 1; n--) {
                d *= (a + (float)n);
                cd = C * d;
                rcu[tid][n - 1] = pack2(cd, cd);
            }
            rcu[tid][NLMAX]     = pack2(a, sp);
            rcu[tid][NLMAX + 1] = pack2(sp * dt, sp * F_TAU);
        }
    }
    __syncthreads();

    const int rl  = tid / TPR;
    const int l   = tid - rl * TPR;
    const int jb  = l * 4;               // lane-contiguous base within each stripe
    const int row = blockIdx.x * RPB + rl;
    if (row >= rows) return;

    const uint32_t rb  = (uint32_t)__cvta_generic_to_shared(&rcu[rl][0]);
    const uint32_t cpb = (uint32_t)__cvta_generic_to_shared(cpos);

    // coefficients into pinned register pairs (constant indices -> registers)
    ull D[NLMAX];
    #pragma unroll
    for (int k = 0; k < NLMAX; k++) D[k] = lds64(rb + k * 8);
    ull SC0 = lds64(rb + NLMAX * 8), SC1 = lds64(rb + (NLMAX + 1) * 8);

    float a, sp, q, shift;
    unpack2(SC0, a, sp);
    unpack2(SC1, q, shift);
    const ull A2 = pack2(a, a);

    float* orow = out + (size_t)row * NTT + jb;

    #pragma unroll
    for (int g = 0; g < NGRP; g++) {
        const int nl = NLG[g];           // compile-time after unroll
        const int ns = NSG[g];
        const int go = g * GSTRIDE;      // stripe offset: lanes contiguous inside
        const float4 t4 = *reinterpret_cast<const float4*>(tsh + go + jb);

        ull XL0, XL1, XS0, XS1, HL0, HL1, HS0, HS1;
        {
            float a0 = fmaf(sp, t4.x, -q), a1 = fmaf(sp, t4.y, -q);
            float a2 = fmaf(sp, t4.z, -q), a3 = fmaf(sp, t4.w, -q);
            XL0 = pack2(a0, a1);
            XL1 = pack2(a2, a3);
            XS0 = pack2(fmaxf(a0 - shift, 0.0f), fmaxf(a1 - shift, 0.0f));
            XS1 = pack2(fmaxf(a2 - shift, 0.0f), fmaxf(a3 - shift, 0.0f));
            HL0 = D[nl - 1]; HL1 = D[nl - 1];
            HS0 = D[ns - 1]; HS1 = D[ns - 1];
        }

        // interleave long and short Horner chains (compile-time bounds)
        #pragma unroll
        for (int k = nl - 2; k >= 0; k--) {
            HL0 = ffma2(HL0, XL0, D[k]);
            HL1 = ffma2(HL1, XL1, D[k]);
            if (k <= ns - 2) {
                HS0 = ffma2(HS0, XS0, D[k]);
                HS1 = ffma2(HS1, XS1, D[k]);
            }
        }

        // exponent + combine, per pair of elements
        ull RES[2];
        ull XLp[2] = {XL0, XL1}, XSp[2] = {XS0, XS1};
        ull HLp[2] = {HL0, HL1}, HSp[2] = {HS0, HS1};
        #pragma unroll
        for (int pp = 0; pp < 2; pp++) {
            float x10, x11, x20, x21;
            unpack2(XLp[pp], x10, x11);
            unpack2(XSp[pp], x20, x21);
            ull LL = pack2(fast_lg2(x10), fast_lg2(x11));
            ull LS = pack2(fast_lg2(x20), fast_lg2(x21));
            ull NE = nl2e_imm();                // {-log2e,-log2e}, transient
            ull ML = fmul2(XLp[pp], NE);        // {-x*log2e, ...}
            ull MS = fmul2(XSp[pp], NE);
            ull VL = ffma2(A2, LL, ML);         // a*lg2(x) - x*log2e
            ull VS = ffma2(A2, LS, MS);         // x2==0 -> -inf -> ex2=0
            float vl0, vl1, vs0, vs1;
            unpack2(VL, vl0, vl1);
            unpack2(VS, vs0, vs1);
            ull EL = pack2(fast_ex2(vl0), fast_ex2(vl1));
            ull ES = pack2(fast_ex2(vs0), fast_ex2(vs1));
            ull PL = fmul2(EL, HLp[pp]);
            ull PS = fmul2(ES, HSp[pp]);
            ull DIF = fadd2(PL, neg2(PS));      // P1 - P2 (xor sign-flip, no const reg)
            ull CP  = lds64(cpb + (uint32_t)(go + jb + pp * 2) * 4u);
            RES[pp] = fmul2(CP, DIF);           // c*(P1 - P2)
        }

        float r0, r1, r2, r3;
        unpack2(RES[0], r0, r1);
        unpack2(RES[1], r2, r3);
        *reinterpret_cast<float4*>(orow + go) = make_float4(r0, r1, r2, r3);
    }
}

extern "C" void kernel_launch(void* const* d_in, const int* in_sizes, int n_in,
                              void* d_out, int out_size) {
    const float4* x     = (const float4*)d_in[0];
    const float*  t     = (const float*)d_in[1];
    const float*  alpha = (const float*)d_in[2];
    const float*  R     = (const float*)d_in[3];
    float* out = (float*)d_out;

    int rows   = in_sizes[0] / 4;
    int blocks = (rows + RPB - 1) / RPB;
    dynangio_kernel<<<blocks, BLK>>>(x, t, alpha, R, out, rows);
}

// round 16
// speedup vs baseline: 1.6557x; 1.6557x over previous
#include <cuda_runtime.h>
#include <cstdint>

#define NTT 144
#define NLMAX 14
#define RPB 32                    // rows per block
#define TPR 4                     // threads per row
#define NGRP 9                    // element offset = g*16 + l*4
#define GSTRIDE 16
#define BLK (RPB * TPR)           // 128 = 4 full warps
#define RCS 17                    // rcu row stride in ull (136B -> bank-conflict-free)

#define F_TAU 1.8f
#define F_INV_T1B (1.0f/1.65f)
#define F_LOG2E 1.4426950408889634f
#define F_DEG2RAD 0.017453292519943295f

typedef unsigned long long ull;

// per-stripe series depths, calibrated to the same tail level as 14 terms @ x=6.27
__device__ constexpr int NLG[NGRP] = {9, 9, 10, 11, 11, 12, 13, 13, 14};
__device__ constexpr int NSG[NGRP] = {4, 5,  6,  6,  7,  8,  8,  9, 10};

__device__ __forceinline__ ull pack2(float lo, float hi) {
    ull r;
    asm("mov.b64 %0, {%1, %2};" : "=l"(r) : "f"(lo), "f"(hi));
    return r;
}
__device__ __forceinline__ void unpack2(ull v, float& lo, float& hi) {
    asm("mov.b64 {%0, %1}, %2;" : "=f"(lo), "=f"(hi) : "l"(v));
}
__device__ __forceinline__ ull ffma2(ull a, ull b, ull c) {
    ull d;
    asm("fma.rn.f32x2 %0, %1, %2, %3;" : "=l"(d) : "l"(a), "l"(b), "l"(c));
    return d;
}
__device__ __forceinline__ float fast_lg2(float x) {
    float r;
    asm("lg2.approx.f32 %0, %1;" : "=f"(r) : "f"(x));
    return r;
}
__device__ __forceinline__ float fast_ex2(float x) {
    float r;
    asm("ex2.approx.f32 %0, %1;" : "=f"(r) : "f"(x));
    return r;
}
// forced single load into a register pair — ptxas cannot rematerialize this
__device__ __forceinline__ ull lds64(uint32_t saddr) {
    ull v;
    asm volatile("ld.shared.b64 %0, [%1];" : "=l"(v) : "r"(saddr));
    return v;
}

__global__ __launch_bounds__(BLK, 10)
void dynangio_kernel(const float4* __restrict__ x,
                     const float*  __restrict__ t,
                     const float*  __restrict__ alpha,
                     const float*  __restrict__ R,
                     float*        __restrict__ out,
                     int rows)
{
    __shared__ __align__(16) float tsh[NTT];
    __shared__ __align__(16) float cpos[NTT];   //  R*sin(alpha)
    // per-row packed coefficients {d,d} (C folded in), + packed scalars:
    // [NLMAX] = {a, sp}, [NLMAX+1] = {q, shift}; padded stride RCS for banks
    __shared__ __align__(16) ull rcu[RPB][RCS];

    const int tid = threadIdx.x;

    for (int j = tid; j < NTT; j += BLK) {
        tsh[j] = t[j];
        cpos[j] = R[j] * __sinf(alpha[j] * F_DEG2RAD);
    }

    if (tid < RPB) {
        int row = blockIdx.x * RPB + tid;
        if (row < rows) {
            float4 xv = x[row];
            float dt  = xv.x;
            float s   = xv.y;
            float p   = xv.z;
            float amp = xv.w;

            float u  = p * s;          // a - 1 in [0,1)
            float a  = 1.0f + u;
            float sp = s + F_INV_T1B;  // sprime

            // C = amp * 2 * exp(-dt/T1B) * (s/sp)^a   (base-2)
            float ratio = __fdividef(s, sp);
            float ex = fmaf(a, fast_lg2(ratio), -dt * (F_LOG2E * F_INV_T1B));
            float C  = amp * 2.0f * fast_ex2(ex);

            // Gamma(1+u), A&S 6.1.36
            float g;
            g = fmaf(u,  0.035868343f, -0.193527818f);
            g = fmaf(u, g,  0.482199394f);
            g = fmaf(u, g, -0.756704078f);
            g = fmaf(u, g,  0.918206857f);
            g = fmaf(u, g, -0.897056937f);
            g = fmaf(u, g,  0.988205891f);
            g = fmaf(u, g, -0.577191652f);
            g = fmaf(u, g,  1.0f);

            // Gamma(a+NLMAX) by product, one reciprocal, build d_n downward
            float prod = a * g;
            #pragma unroll
            for (int k = 1; k < NLMAX; k++) prod *= (a + (float)k);
            float d = __frcp_rn(prod);
            float cd = C * d;
            rcu[tid][NLMAX - 1] = pack2(cd, cd);
            #pragma unroll
            for (int n = NLMAX - 1; n >= 1; n--) {
                d *= (a + (float)n);
                cd = C * d;
                rcu[tid][n - 1] = pack2(cd, cd);
            }
            rcu[tid][NLMAX]     = pack2(a, sp);
            rcu[tid][NLMAX + 1] = pack2(sp * dt, sp * F_TAU);
        }
    }
    __syncthreads();

    const int rl  = tid / TPR;
    const int l   = tid - rl * TPR;
    const int jb  = l * 4;               // lane-contiguous base within each stripe
    const int row = blockIdx.x * RPB + rl;
    if (row >= rows) return;

    const uint32_t rb = (uint32_t)__cvta_generic_to_shared(&rcu[rl][0]);

    // coefficients into pinned register pairs (constant indices -> registers)
    ull D[NLMAX];
    #pragma unroll
    for (int k = 0; k < NLMAX; k++) D[k] = lds64(rb + k * 8);
    ull SC0 = lds64(rb + NLMAX * 8), SC1 = lds64(rb + (NLMAX + 1) * 8);

    float a, sp, q, shift;
    unpack2(SC0, a, sp);
    unpack2(SC1, q, shift);
    const float sl = shift * F_LOG2E;    // m2 = m1 + sl

    float* orow = out + (size_t)row * NTT + jb;

    #pragma unroll
    for (int g = 0; g < NGRP; g++) {
        const int nl = NLG[g];           // compile-time after unroll
        const int ns = NSG[g];
        const int go = g * GSTRIDE;      // stripe offset: lanes contiguous inside
        const float4 t4 = *reinterpret_cast<const float4*>(tsh + go + jb);

        ull XL0, XL1, XS0, XS1, HL0, HL1, HS0, HS1;
        {
            float a0 = fmaf(sp, t4.x, -q), a1 = fmaf(sp, t4.y, -q);
            float a2 = fmaf(sp, t4.z, -q), a3 = fmaf(sp, t4.w, -q);
            XL0 = pack2(a0, a1);
            XL1 = pack2(a2, a3);
            XS0 = pack2(fmaxf(a0 - shift, 0.0f), fmaxf(a1 - shift, 0.0f));
            XS1 = pack2(fmaxf(a2 - shift, 0.0f), fmaxf(a3 - shift, 0.0f));
            HL0 = D[nl - 1]; HL1 = D[nl - 1];
            HS0 = D[ns - 1]; HS1 = D[ns - 1];
        }

        // interleave long and short Horner chains (compile-time bounds)
        #pragma unroll
        for (int k = nl - 2; k >= 0; k--) {
            HL0 = ffma2(HL0, XL0, D[k]);
            HL1 = ffma2(HL1, XL1, D[k]);
            if (k <= ns - 2) {
                HS0 = ffma2(HS0, XS0, D[k]);
                HS1 = ffma2(HS1, XS1, D[k]);
            }
        }

        // fully scalar epilogue — no pack/unpack around MUFU ops
        float x1v[4], x2v[4], h1v[4], h2v[4];
        unpack2(XL0, x1v[0], x1v[1]);
        unpack2(XL1, x1v[2], x1v[3]);
        unpack2(XS0, x2v[0], x2v[1]);
        unpack2(XS1, x2v[2], x2v[3]);
        unpack2(HL0, h1v[0], h1v[1]);
        unpack2(HL1, h1v[2], h1v[3]);
        unpack2(HS0, h2v[0], h2v[1]);
        unpack2(HS1, h2v[2], h2v[3]);

        const float4 c4 = *reinterpret_cast<const float4*>(cpos + go + jb);
        float cv[4] = {c4.x, c4.y, c4.z, c4.w};

        float res[4];
        #pragma unroll
        for (int e = 0; e < 4; e++) {
            float x1 = x1v[e], x2 = x2v[e];
            float m1 = x1 * (-F_LOG2E);          // independent of lg2 chain
            float v1 = fmaf(a, fast_lg2(x1), m1);
            float v2 = fmaf(a, fast_lg2(x2), m1 + sl);  // x2==0 -> -inf -> ex2=0
            float P1 = fast_ex2(v1) * h1v[e];
            float P2 = fast_ex2(v2) * h2v[e];
            res[e] = cv[e] * (P1 - P2);
        }
        *reinterpret_cast<float4*>(orow + go) =
            make_float4(res[0], res[1], res[2], res[3]);
    }
}

extern "C" void kernel_launch(void* const* d_in, const int* in_sizes, int n_in,
                              void* d_out, int out_size) {
    const float4* x     = (const float4*)d_in[0];
    const float*  t     = (const float*)d_in[1];
    const float*  alpha = (const float*)d_in[2];
    const float*  R     = (const float*)d_in[3];
    float* out = (float*)d_out;

    int rows   = in_sizes[0] / 4;
    int blocks = (rows + RPB - 1) / RPB;
    dynangio_kernel<<<blocks, BLK>>>(x, t, alpha, R, out, rows);
}